// round 2
// baseline (speedup 1.0000x reference)
#include <cuda_runtime.h>
#include <math.h>

// Problem constants (fixed shapes per reference)
#define NN   40000
#define EE   640000
#define GG   64
#define HH   4
#define CC   64
#define HC   256      // H*C
#define NHID 1024
#define NOUT 768
#define NEG_SLOPE 0.2f

// ---------------- static device scratch (no runtime allocation) ----------------
__device__ float g_bufA[(size_t)NN * HC];   // post-GEMM features h
__device__ float g_bufB[(size_t)NN * HC];   // aggregated output / next layer input
__device__ float g_w4[(size_t)EE * 4];      // per-edge exp weights, 4 heads
__device__ float g_as[NN * 4];              // alpha_src per node/head
__device__ float g_ad[NN * 4];              // alpha_dst per node/head
__device__ int   g_cnt[NN];
__device__ int   g_cur[NN];
__device__ int   g_off[NN + 1];
__device__ int2  g_csr[EE];                 // (src, edge_id) sorted by dst
__device__ int   g_gcnt[GG];
__device__ int   g_goff[GG + 1];
__device__ float g_pooled[GG * HC];
__device__ float g_hid[GG * NHID];
__device__ int   g_is64_e;                  // edge_index is int64?
__device__ int   g_is64_b;                  // batch is int64?

__device__ __forceinline__ float lrelu(float v) {
    return v > 0.f ? v : NEG_SLOPE * v;
}

// Read logical element i of an index array that may be int32 or int64.
__device__ __forceinline__ int idx_at(const void* p, long long i, int is64) {
    if (is64) return (int)((const long long*)p)[i];
    return ((const int*)p)[i];
}

// ---------------- dtype detection ----------------
// int64 (LE, non-negative, < 2^31): every odd 32-bit word is 0.
// int32 random ids / sorted batch tail: essentially never 64 zeros in a row.
__global__ void k_detect(const void* ei, const void* batch) {
    if (threadIdx.x != 0 || blockIdx.x != 0) return;
    const int* e32 = (const int*)ei;
    int all0 = 1;
    for (int j = 1; j < 128; j += 2) {
        if (e32[j] != 0) { all0 = 0; break; }
    }
    g_is64_e = all0;
    const int* b32 = (const int*)batch;
    all0 = 1;
    // inspect the tail (sorted batch => tail values ~G-1, nonzero if int32)
    for (int j = NN - 1; j > NN - 65; j -= 2) {    // odd indices (NN even)
        if (b32[j] != 0) { all0 = 0; break; }
    }
    g_is64_b = all0;
}

// ---------------- CSR construction ----------------
__global__ void k_zero() {
    int i = blockIdx.x * blockDim.x + threadIdx.x;
    if (i < NN) { g_cnt[i] = 0; g_cur[i] = 0; }
    if (i < GG) { g_gcnt[i] = 0; }
}

__global__ void k_count(const void* __restrict__ ei) {
    int e = blockIdx.x * blockDim.x + threadIdx.x;
    if (e < EE) {
        int d = idx_at(ei, (long long)EE + e, g_is64_e);
        atomicAdd(&g_cnt[d], 1);
    }
}

__global__ void k_gcount(const void* __restrict__ batch) {
    int n = blockIdx.x * blockDim.x + threadIdx.x;
    if (n < NN) atomicAdd(&g_gcnt[idx_at(batch, n, g_is64_b)], 1);
}

// single-block exclusive scan (n up to ~40k, looped in chunks of 1024)
__global__ void k_scan(const int* __restrict__ cnt, int* __restrict__ off, int n) {
    __shared__ int sd[1024];
    __shared__ int carry;
    int t = threadIdx.x;
    if (t == 0) carry = 0;
    __syncthreads();
    for (int base = 0; base < n; base += 1024) {
        int v = (base + t < n) ? cnt[base + t] : 0;
        sd[t] = v;
        __syncthreads();
        for (int o = 1; o < 1024; o <<= 1) {
            int y = (t >= o) ? sd[t - o] : 0;
            __syncthreads();
            sd[t] += y;
            __syncthreads();
        }
        if (base + t < n) off[base + t] = carry + sd[t] - v;
        __syncthreads();
        if (t == 0) carry += sd[1023];
        __syncthreads();
    }
    if (t == 0) off[n] = carry;
}

__global__ void k_fill(const void* __restrict__ ei) {
    int e = blockIdx.x * blockDim.x + threadIdx.x;
    if (e >= EE) return;
    int is64 = g_is64_e;
    int s = idx_at(ei, e, is64);
    int d = idx_at(ei, (long long)EE + e, is64);
    int pos = atomicAdd(&g_cur[d], 1);
    g_csr[g_off[d] + pos] = make_int2(s, e);
}

// ---------------- GEMM: C[M,256] = A[M,256] @ B[256,256], fp32 ----------------
// Tiles: 64x64, block 256 threads, thread tile 4x4. M=40000 divisible by 64.
__global__ void k_gemm(const float* __restrict__ A, const float* __restrict__ B,
                       float* __restrict__ C) {
    __shared__ float As[16][64];
    __shared__ float Bs[16][64];
    int tid = threadIdx.x;
    int tx = tid & 15, ty = tid >> 4;
    int row0 = blockIdx.x * 64;
    int col0 = blockIdx.y * 64;
    float acc[4][4];
#pragma unroll
    for (int i = 0; i < 4; i++)
#pragma unroll
        for (int j = 0; j < 4; j++) acc[i][j] = 0.f;

    int ar = tid >> 2;            // 0..63
    int akk = (tid & 3) * 4;      // 0..12
    int br = tid >> 4;            // 0..15
    int bc = (tid & 15) * 4;      // 0..60

    for (int k0 = 0; k0 < 256; k0 += 16) {
        float4 av = *(const float4*)(A + (size_t)(row0 + ar) * 256 + k0 + akk);
        As[akk + 0][ar] = av.x;
        As[akk + 1][ar] = av.y;
        As[akk + 2][ar] = av.z;
        As[akk + 3][ar] = av.w;
        float4 bv = *(const float4*)(B + (size_t)(k0 + br) * 256 + col0 + bc);
        *(float4*)&Bs[br][bc] = bv;
        __syncthreads();
#pragma unroll
        for (int k = 0; k < 16; k++) {
            float ax[4], bx[4];
            *(float4*)ax = *(float4*)&As[k][ty * 4];
            *(float4*)bx = *(float4*)&Bs[k][tx * 4];
#pragma unroll
            for (int i = 0; i < 4; i++)
#pragma unroll
                for (int j = 0; j < 4; j++) acc[i][j] += ax[i] * bx[j];
        }
        __syncthreads();
    }
#pragma unroll
    for (int i = 0; i < 4; i++) {
        float4 o = make_float4(acc[i][0], acc[i][1], acc[i][2], acc[i][3]);
        *(float4*)(C + (size_t)(row0 + ty * 4 + i) * 256 + col0 + tx * 4) = o;
    }
}

// ---------------- per-node attention scalars ----------------
__global__ void k_alpha(const float* __restrict__ h, const float* __restrict__ a_s,
                        const float* __restrict__ a_d) {
    int gw = (blockIdx.x * blockDim.x + threadIdx.x) >> 5;
    int lane = threadIdx.x & 31;
    if (gw >= NN) return;
    const float* row = h + (size_t)gw * HC;
#pragma unroll
    for (int hh = 0; hh < HH; hh++) {
        float v1 = row[hh * 64 + lane];
        float v2 = row[hh * 64 + 32 + lane];
        float ps = v1 * __ldg(&a_s[hh * 64 + lane]) + v2 * __ldg(&a_s[hh * 64 + 32 + lane]);
        float pd = v1 * __ldg(&a_d[hh * 64 + lane]) + v2 * __ldg(&a_d[hh * 64 + 32 + lane]);
#pragma unroll
        for (int o = 16; o > 0; o >>= 1) {
            ps += __shfl_down_sync(0xffffffffu, ps, o);
            pd += __shfl_down_sync(0xffffffffu, pd, o);
        }
        if (lane == 0) {
            g_as[gw * 4 + hh] = ps;
            g_ad[gw * 4 + hh] = pd;
        }
    }
}

// ---------------- per-edge softmax weights (un-normalized) ----------------
__global__ void k_edgew(const void* __restrict__ ei) {
    int e = blockIdx.x * blockDim.x + threadIdx.x;
    if (e >= EE) return;
    int is64 = g_is64_e;
    int s = idx_at(ei, e, is64);
    int d = idx_at(ei, (long long)EE + e, is64);
    float4 a = *(const float4*)(g_as + s * 4);
    float4 b = *(const float4*)(g_ad + d * 4);
    float4 wv;
    wv.x = expf(lrelu(a.x + b.x));
    wv.y = expf(lrelu(a.y + b.y));
    wv.z = expf(lrelu(a.z + b.z));
    wv.w = expf(lrelu(a.w + b.w));
    ((float4*)g_w4)[e] = wv;
}

// ---------------- warp-per-node gather (no atomics) ----------------
template <bool RELU>
__global__ void k_gather(const float* __restrict__ h, const float* __restrict__ bias,
                         float* __restrict__ out) {
    int gw = (blockIdx.x * blockDim.x + threadIdx.x) >> 5;
    int lane = threadIdx.x & 31;
    if (gw >= NN) return;
    int s0 = g_off[gw], s1 = g_off[gw + 1];
    float acc[8];
#pragma unroll
    for (int k = 0; k < 8; k++) acc[k] = 0.f;
    float dsum0 = 0.f, dsum1 = 0.f, dsum2 = 0.f, dsum3 = 0.f;

    for (int i = s0; i < s1; i++) {
        int2 se = __ldg(&g_csr[i]);
        float4 wv = __ldg((const float4*)g_w4 + se.y);
        const float* hs = h + (size_t)se.x * HC;
        dsum0 += wv.x; dsum1 += wv.y; dsum2 += wv.z; dsum3 += wv.w;
        float wl[4] = {wv.x, wv.y, wv.z, wv.w};
#pragma unroll
        for (int k = 0; k < 8; k++) {
            acc[k] += wl[k >> 1] * __ldg(&hs[lane + 32 * k]);
        }
    }
    // self loop (reference appends one per node)
    float4 av = *(const float4*)(g_as + gw * 4);
    float4 dv = *(const float4*)(g_ad + gw * 4);
    float ws[4];
    ws[0] = expf(lrelu(av.x + dv.x));
    ws[1] = expf(lrelu(av.y + dv.y));
    ws[2] = expf(lrelu(av.z + dv.z));
    ws[3] = expf(lrelu(av.w + dv.w));
    float den[4] = {dsum0 + ws[0], dsum1 + ws[1], dsum2 + ws[2], dsum3 + ws[3]};
    const float* hn = h + (size_t)gw * HC;
    float* orow = out + (size_t)gw * HC;
#pragma unroll
    for (int k = 0; k < 8; k++) {
        int c = lane + 32 * k;
        int hh = k >> 1;
        float v = (acc[k] + ws[hh] * __ldg(&hn[c])) / den[hh] + __ldg(&bias[c]);
        if (RELU) v = fmaxf(v, 0.f);
        orow[c] = v;
    }
}

// ---------------- pooling + MLP head ----------------
__global__ void k_pool(const float* __restrict__ h3) {
    int g = blockIdx.x;
    int c = threadIdx.x;   // 256
    int s = g_goff[g], e = g_goff[g + 1];
    float sum = 0.f;
    for (int n = s; n < e; n++) sum += h3[(size_t)n * HC + c];
    float cntf = (float)(e - s);
    g_pooled[g * HC + c] = sum / fmaxf(cntf, 1.0f);
}

__global__ void k_mlp1(const float* __restrict__ Wm1, const float* __restrict__ bm1) {
    __shared__ float sp[HC];
    int g = blockIdx.x;
    int j = threadIdx.x;   // 1024
    if (j < HC) sp[j] = g_pooled[g * HC + j];
    __syncthreads();
    float acc = __ldg(&bm1[j]);
    for (int k = 0; k < HC; k++) acc += sp[k] * __ldg(&Wm1[(size_t)k * NHID + j]);
    g_hid[g * NHID + j] = fmaxf(acc, 0.f);
}

__global__ void k_mlp2(const float* __restrict__ Wm2, const float* __restrict__ bm2,
                       float* __restrict__ out) {
    __shared__ float sp[NHID];
    int g = blockIdx.x;
    int j = threadIdx.x;   // 768
    for (int k = j; k < NHID; k += NOUT) sp[k] = g_hid[g * NHID + k];
    __syncthreads();
    float acc = __ldg(&bm2[j]);
    for (int k = 0; k < NHID; k++) acc += sp[k] * __ldg(&Wm2[(size_t)k * NOUT + j]);
    out[g * NOUT + j] = acc;
}

// ---------------- launch ----------------
extern "C" void kernel_launch(void* const* d_in, const int* in_sizes, int n_in,
                              void* d_out, int out_size) {
    const float* x     = (const float*)d_in[0];
    const void*  ei    = d_in[1];
    const void*  batch = d_in[2];
    const float* W1  = (const float*)d_in[3];
    const float* as1 = (const float*)d_in[4];
    const float* ad1 = (const float*)d_in[5];
    const float* b1  = (const float*)d_in[6];
    const float* W2  = (const float*)d_in[7];
    const float* as2 = (const float*)d_in[8];
    const float* ad2 = (const float*)d_in[9];
    const float* b2  = (const float*)d_in[10];
    const float* W3  = (const float*)d_in[11];
    const float* as3 = (const float*)d_in[12];
    const float* ad3 = (const float*)d_in[13];
    const float* b3  = (const float*)d_in[14];
    const float* Wm1 = (const float*)d_in[15];
    const float* bm1 = (const float*)d_in[16];
    const float* Wm2 = (const float*)d_in[17];
    const float* bm2 = (const float*)d_in[18];
    float* out = (float*)d_out;

    float *bufA, *bufB;
    int *cntp, *offp, *gcntp, *goffp;
    cudaGetSymbolAddress((void**)&bufA, g_bufA);
    cudaGetSymbolAddress((void**)&bufB, g_bufB);
    cudaGetSymbolAddress((void**)&cntp, g_cnt);
    cudaGetSymbolAddress((void**)&offp, g_off);
    cudaGetSymbolAddress((void**)&gcntp, g_gcnt);
    cudaGetSymbolAddress((void**)&goffp, g_goff);

    const int TPB = 256;
    int nb_node = (NN + TPB - 1) / TPB;
    int nb_edge = (EE + TPB - 1) / TPB;
    int nb_warp = (NN * 32 + TPB - 1) / TPB;   // one warp per node

    // dtype detection + CSR build (graph identical for all 3 layers)
    k_detect<<<1, 32>>>(ei, batch);
    k_zero<<<nb_node, TPB>>>();
    k_count<<<nb_edge, TPB>>>(ei);
    k_gcount<<<nb_node, TPB>>>(batch);
    k_scan<<<1, 1024>>>(cntp, offp, NN);
    k_scan<<<1, 1024>>>(gcntp, goffp, GG);
    k_fill<<<nb_edge, TPB>>>(ei);

    dim3 gemm_grid(NN / 64, HC / 64);

    // Layer 1
    k_gemm<<<gemm_grid, 256>>>(x, W1, bufA);
    k_alpha<<<nb_warp, TPB>>>(bufA, as1, ad1);
    k_edgew<<<nb_edge, TPB>>>(ei);
    k_gather<true><<<nb_warp, TPB>>>(bufA, b1, bufB);

    // Layer 2
    k_gemm<<<gemm_grid, 256>>>(bufB, W2, bufA);
    k_alpha<<<nb_warp, TPB>>>(bufA, as2, ad2);
    k_edgew<<<nb_edge, TPB>>>(ei);
    k_gather<true><<<nb_warp, TPB>>>(bufA, b2, bufB);

    // Layer 3 (no relu)
    k_gemm<<<gemm_grid, 256>>>(bufB, W3, bufA);
    k_alpha<<<nb_warp, TPB>>>(bufA, as3, ad3);
    k_edgew<<<nb_edge, TPB>>>(ei);
    k_gather<false><<<nb_warp, TPB>>>(bufA, b3, bufB);

    // Pool + MLP
    k_pool<<<GG, HC>>>(bufB);
    k_mlp1<<<GG, NHID>>>(Wm1, bm1);
    k_mlp2<<<GG, NOUT>>>(Wm2, bm2, out);
}

// round 3
// speedup vs baseline: 1.0913x; 1.0913x over previous
#include <cuda_runtime.h>
#include <math.h>
#include <stdint.h>

// Problem constants (fixed shapes per reference)
#define NN   40000
#define EE   640000
#define GG   64
#define HH   4
#define CC   64
#define HC   256      // H*C
#define NHID 1024
#define NOUT 768
#define NEG_SLOPE 0.2f

// ---------------- static device scratch (no runtime allocation) ----------------
__device__ float g_bufA[(size_t)NN * HC];   // post-GEMM features h
__device__ float g_bufB[(size_t)NN * HC];   // aggregated output / next layer input
__device__ float g_w4[(size_t)EE * 4];      // per-edge exp weights, 4 heads
__device__ float g_as[NN * 4];              // alpha_src per node/head
__device__ float g_ad[NN * 4];              // alpha_dst per node/head
__device__ int   g_cnt[NN];
__device__ int   g_cur[NN];
__device__ int   g_off[NN + 1];
__device__ int2  g_csr[EE];                 // (src, edge_id) sorted by dst
__device__ int   g_goff[GG + 1];
__device__ float g_pooled[GG * HC];
__device__ float g_hid[GG * NHID];
__device__ int   g_is64_e;                  // edge_index is int64?
__device__ int   g_is64_b;                  // batch is int64?

__device__ __forceinline__ float lrelu(float v) {
    return v > 0.f ? v : NEG_SLOPE * v;
}

// Read logical element i of an index array that may be int32 or int64.
__device__ __forceinline__ int idx_at(const void* p, long long i, int is64) {
    if (is64) return (int)((const long long*)p)[i];
    return ((const int*)p)[i];
}

// ---------------- dtype detection ----------------
__global__ void k_detect(const void* ei, const void* batch) {
    if (threadIdx.x != 0 || blockIdx.x != 0) return;
    const int* e32 = (const int*)ei;
    int all0 = 1;
    for (int j = 1; j < 128; j += 2) {
        if (e32[j] != 0) { all0 = 0; break; }
    }
    g_is64_e = all0;
    const int* b32 = (const int*)batch;
    all0 = 1;
    for (int j = NN - 1; j > NN - 65; j -= 2) {    // odd word indices
        if (b32[j] != 0) { all0 = 0; break; }
    }
    g_is64_b = all0;
}

// ---------------- CSR construction ----------------
__global__ void k_zero() {
    int i = blockIdx.x * blockDim.x + threadIdx.x;
    if (i < NN) { g_cnt[i] = 0; g_cur[i] = 0; }
}

__global__ void k_count(const void* __restrict__ ei) {
    int e = blockIdx.x * blockDim.x + threadIdx.x;
    if (e < EE) {
        int d = idx_at(ei, (long long)EE + e, g_is64_e);
        atomicAdd(&g_cnt[d], 1);
    }
}

// batch is sorted: graph boundaries by binary search (replaces atomics+scan)
__global__ void k_gbounds(const void* __restrict__ batch) {
    int g = threadIdx.x;
    if (g > GG) return;
    int is64 = g_is64_b;
    int lo = 0, hi = NN;
    while (lo < hi) {
        int mid = (lo + hi) >> 1;
        if (idx_at(batch, mid, is64) < g) lo = mid + 1; else hi = mid;
    }
    g_goff[g] = lo;
}

// single-block exclusive scan (n up to ~40k, looped in chunks of 1024)
__global__ void k_scan(const int* __restrict__ cnt, int* __restrict__ off, int n) {
    __shared__ int sd[1024];
    __shared__ int carry;
    int t = threadIdx.x;
    if (t == 0) carry = 0;
    __syncthreads();
    for (int base = 0; base < n; base += 1024) {
        int v = (base + t < n) ? cnt[base + t] : 0;
        sd[t] = v;
        __syncthreads();
        for (int o = 1; o < 1024; o <<= 1) {
            int y = (t >= o) ? sd[t - o] : 0;
            __syncthreads();
            sd[t] += y;
            __syncthreads();
        }
        if (base + t < n) off[base + t] = carry + sd[t] - v;
        __syncthreads();
        if (t == 0) carry += sd[1023];
        __syncthreads();
    }
    if (t == 0) off[n] = carry;
}

__global__ void k_fill(const void* __restrict__ ei) {
    int e = blockIdx.x * blockDim.x + threadIdx.x;
    if (e >= EE) return;
    int is64 = g_is64_e;
    int s = idx_at(ei, e, is64);
    int d = idx_at(ei, (long long)EE + e, is64);
    int pos = atomicAdd(&g_cur[d], 1);
    g_csr[g_off[d] + pos] = make_int2(s, e);
}

// ---------------- tf32 split-precision tensor-core GEMM ----------------
// C[M,256] = A[M,256] @ B[256,256], fp32-accurate via hi/lo tf32 decomposition.
// Block: 64x64 tile, 128 threads (4 warps, 2x2 of 32x32 warp tiles), BK=32.

__device__ __forceinline__ void split_tf32(float x, float& hi, float& lo) {
    uint32_t u;
    asm("cvt.rna.tf32.f32 %0, %1;" : "=r"(u) : "f"(x));
    hi = __uint_as_float(u);
    float l = x - hi;
    uint32_t ul;
    asm("cvt.rna.tf32.f32 %0, %1;" : "=r"(ul) : "f"(l));
    lo = __uint_as_float(ul);
}

__device__ __forceinline__ void mma_tf32(float* d, const uint32_t* a, const uint32_t* b) {
    asm volatile(
        "mma.sync.aligned.m16n8k8.row.col.f32.tf32.tf32.f32 "
        "{%0,%1,%2,%3}, {%4,%5,%6,%7}, {%8,%9}, {%0,%1,%2,%3};\n"
        : "+f"(d[0]), "+f"(d[1]), "+f"(d[2]), "+f"(d[3])
        : "r"(a[0]), "r"(a[1]), "r"(a[2]), "r"(a[3]), "r"(b[0]), "r"(b[1]));
}

#define AS_STR 36   // A smem row stride (padded, 16B-aligned, conflict-free frags)
#define BS_STR 72   // B smem row stride (stride%32==8 -> conflict-free frags)

__global__ void __launch_bounds__(128) k_gemm_tc(const float* __restrict__ A,
                                                 const float* __restrict__ B,
                                                 float* __restrict__ C) {
    __shared__ float As_hi[64][AS_STR], As_lo[64][AS_STR];
    __shared__ float Bs_hi[32][BS_STR], Bs_lo[32][BS_STR];

    int tid = threadIdx.x;
    int warp = tid >> 5, lane = tid & 31;
    int wm = (warp & 1) * 32;         // warp row offset in tile
    int wn = (warp >> 1) * 32;        // warp col offset in tile
    int lm = lane >> 2;               // 0..7
    int lk = lane & 3;                // 0..3
    int row0 = blockIdx.x * 64;
    int col0 = blockIdx.y * 64;

    float acc[2][4][4];
#pragma unroll
    for (int mt = 0; mt < 2; mt++)
#pragma unroll
        for (int nt = 0; nt < 4; nt++)
#pragma unroll
            for (int r = 0; r < 4; r++) acc[mt][nt][r] = 0.f;

    // global->smem mapping
    int am = tid >> 1;                // A row 0..63
    int akseg = (tid & 1) * 16;       // A k seg
    int bk = tid >> 2;                // B k row 0..31
    int bnseg = (tid & 3) * 16;       // B n seg

    for (int k0 = 0; k0 < 256; k0 += 32) {
#pragma unroll
        for (int i = 0; i < 4; i++) {
            int k = akseg + i * 4;
            float4 v = *(const float4*)(A + (size_t)(row0 + am) * 256 + k0 + k);
            float4 vh, vl;
            split_tf32(v.x, vh.x, vl.x);
            split_tf32(v.y, vh.y, vl.y);
            split_tf32(v.z, vh.z, vl.z);
            split_tf32(v.w, vh.w, vl.w);
            *(float4*)&As_hi[am][k] = vh;
            *(float4*)&As_lo[am][k] = vl;
        }
#pragma unroll
        for (int i = 0; i < 4; i++) {
            int n = bnseg + i * 4;
            float4 v = *(const float4*)(B + (size_t)(k0 + bk) * 256 + col0 + n);
            float4 vh, vl;
            split_tf32(v.x, vh.x, vl.x);
            split_tf32(v.y, vh.y, vl.y);
            split_tf32(v.z, vh.z, vl.z);
            split_tf32(v.w, vh.w, vl.w);
            *(float4*)&Bs_hi[bk][n] = vh;
            *(float4*)&Bs_lo[bk][n] = vl;
        }
        __syncthreads();

#pragma unroll
        for (int kk = 0; kk < 32; kk += 8) {
            uint32_t ah[2][4], al[2][4];
#pragma unroll
            for (int mt = 0; mt < 2; mt++) {
                int r = wm + mt * 16 + lm;
                ah[mt][0] = __float_as_uint(As_hi[r][kk + lk]);
                ah[mt][1] = __float_as_uint(As_hi[r + 8][kk + lk]);
                ah[mt][2] = __float_as_uint(As_hi[r][kk + lk + 4]);
                ah[mt][3] = __float_as_uint(As_hi[r + 8][kk + lk + 4]);
                al[mt][0] = __float_as_uint(As_lo[r][kk + lk]);
                al[mt][1] = __float_as_uint(As_lo[r + 8][kk + lk]);
                al[mt][2] = __float_as_uint(As_lo[r][kk + lk + 4]);
                al[mt][3] = __float_as_uint(As_lo[r + 8][kk + lk + 4]);
            }
            uint32_t bh[4][2], bl[4][2];
#pragma unroll
            for (int nt = 0; nt < 4; nt++) {
                int c = wn + nt * 8 + lm;
                bh[nt][0] = __float_as_uint(Bs_hi[kk + lk][c]);
                bh[nt][1] = __float_as_uint(Bs_hi[kk + lk + 4][c]);
                bl[nt][0] = __float_as_uint(Bs_lo[kk + lk][c]);
                bl[nt][1] = __float_as_uint(Bs_lo[kk + lk + 4][c]);
            }
#pragma unroll
            for (int mt = 0; mt < 2; mt++)
#pragma unroll
                for (int nt = 0; nt < 4; nt++) {
                    mma_tf32(acc[mt][nt], ah[mt], bh[nt]);
                    mma_tf32(acc[mt][nt], ah[mt], bl[nt]);
                    mma_tf32(acc[mt][nt], al[mt], bh[nt]);
                }
        }
        __syncthreads();
    }

    // store C
#pragma unroll
    for (int mt = 0; mt < 2; mt++) {
        int r = row0 + wm + mt * 16 + lm;
#pragma unroll
        for (int nt = 0; nt < 4; nt++) {
            int c = col0 + wn + nt * 8 + lk * 2;
            *(float2*)(C + (size_t)r * 256 + c)       = make_float2(acc[mt][nt][0], acc[mt][nt][1]);
            *(float2*)(C + (size_t)(r + 8) * 256 + c) = make_float2(acc[mt][nt][2], acc[mt][nt][3]);
        }
    }
}

// ---------------- per-node attention scalars ----------------
__global__ void k_alpha(const float* __restrict__ h, const float* __restrict__ a_s,
                        const float* __restrict__ a_d) {
    int gw = (blockIdx.x * blockDim.x + threadIdx.x) >> 5;
    int lane = threadIdx.x & 31;
    if (gw >= NN) return;
    const float* row = h + (size_t)gw * HC;
#pragma unroll
    for (int hh = 0; hh < HH; hh++) {
        float v1 = row[hh * 64 + lane];
        float v2 = row[hh * 64 + 32 + lane];
        float ps = v1 * __ldg(&a_s[hh * 64 + lane]) + v2 * __ldg(&a_s[hh * 64 + 32 + lane]);
        float pd = v1 * __ldg(&a_d[hh * 64 + lane]) + v2 * __ldg(&a_d[hh * 64 + 32 + lane]);
#pragma unroll
        for (int o = 16; o > 0; o >>= 1) {
            ps += __shfl_down_sync(0xffffffffu, ps, o);
            pd += __shfl_down_sync(0xffffffffu, pd, o);
        }
        if (lane == 0) {
            g_as[gw * 4 + hh] = ps;
            g_ad[gw * 4 + hh] = pd;
        }
    }
}

// ---------------- per-edge softmax weights (un-normalized) ----------------
__global__ void k_edgew(const void* __restrict__ ei) {
    int e = blockIdx.x * blockDim.x + threadIdx.x;
    if (e >= EE) return;
    int is64 = g_is64_e;
    int s = idx_at(ei, e, is64);
    int d = idx_at(ei, (long long)EE + e, is64);
    float4 a = *(const float4*)(g_as + s * 4);
    float4 b = *(const float4*)(g_ad + d * 4);
    float4 wv;
    wv.x = expf(lrelu(a.x + b.x));
    wv.y = expf(lrelu(a.y + b.y));
    wv.z = expf(lrelu(a.z + b.z));
    wv.w = expf(lrelu(a.w + b.w));
    ((float4*)g_w4)[e] = wv;
}

// ---------------- warp-per-node gather (no atomics) ----------------
template <bool RELU>
__global__ void k_gather(const float* __restrict__ h, const float* __restrict__ bias,
                         float* __restrict__ out) {
    int gw = (blockIdx.x * blockDim.x + threadIdx.x) >> 5;
    int lane = threadIdx.x & 31;
    if (gw >= NN) return;
    int s0 = g_off[gw], s1 = g_off[gw + 1];
    float acc[8];
#pragma unroll
    for (int k = 0; k < 8; k++) acc[k] = 0.f;
    float dsum0 = 0.f, dsum1 = 0.f, dsum2 = 0.f, dsum3 = 0.f;

    for (int i = s0; i < s1; i++) {
        int2 se = __ldg(&g_csr[i]);
        float4 wv = __ldg((const float4*)g_w4 + se.y);
        const float* hs = h + (size_t)se.x * HC;
        dsum0 += wv.x; dsum1 += wv.y; dsum2 += wv.z; dsum3 += wv.w;
        float wl[4] = {wv.x, wv.y, wv.z, wv.w};
#pragma unroll
        for (int k = 0; k < 8; k++) {
            acc[k] += wl[k >> 1] * __ldg(&hs[lane + 32 * k]);
        }
    }
    // self loop (reference appends one per node)
    float4 av = *(const float4*)(g_as + gw * 4);
    float4 dv = *(const float4*)(g_ad + gw * 4);
    float ws[4];
    ws[0] = expf(lrelu(av.x + dv.x));
    ws[1] = expf(lrelu(av.y + dv.y));
    ws[2] = expf(lrelu(av.z + dv.z));
    ws[3] = expf(lrelu(av.w + dv.w));
    float den[4] = {dsum0 + ws[0], dsum1 + ws[1], dsum2 + ws[2], dsum3 + ws[3]};
    const float* hn = h + (size_t)gw * HC;
    float* orow = out + (size_t)gw * HC;
#pragma unroll
    for (int k = 0; k < 8; k++) {
        int c = lane + 32 * k;
        int hh = k >> 1;
        float v = (acc[k] + ws[hh] * __ldg(&hn[c])) / den[hh] + __ldg(&bias[c]);
        if (RELU) v = fmaxf(v, 0.f);
        orow[c] = v;
    }
}

// ---------------- pooling + MLP head ----------------
__global__ void k_pool(const float* __restrict__ h3) {
    int g = blockIdx.x;
    int c = threadIdx.x;   // 256
    int s = g_goff[g], e = g_goff[g + 1];
    float sum = 0.f;
    for (int n = s; n < e; n++) sum += h3[(size_t)n * HC + c];
    float cntf = (float)(e - s);
    g_pooled[g * HC + c] = sum / fmaxf(cntf, 1.0f);
}

__global__ void k_mlp1(const float* __restrict__ Wm1, const float* __restrict__ bm1) {
    __shared__ float sp[HC];
    int g = blockIdx.x;
    int j = threadIdx.x;   // 1024
    if (j < HC) sp[j] = g_pooled[g * HC + j];
    __syncthreads();
    float acc = __ldg(&bm1[j]);
    for (int k = 0; k < HC; k++) acc += sp[k] * __ldg(&Wm1[(size_t)k * NHID + j]);
    g_hid[g * NHID + j] = fmaxf(acc, 0.f);
}

__global__ void k_mlp2(const float* __restrict__ Wm2, const float* __restrict__ bm2,
                       float* __restrict__ out) {
    __shared__ float sp[NHID];
    int g = blockIdx.x;
    int j = threadIdx.x;   // 768
    for (int k = j; k < NHID; k += NOUT) sp[k] = g_hid[g * NHID + k];
    __syncthreads();
    float acc = __ldg(&bm2[j]);
    for (int k = 0; k < NHID; k++) acc += sp[k] * __ldg(&Wm2[(size_t)k * NOUT + j]);
    out[g * NOUT + j] = acc;
}

// ---------------- launch ----------------
extern "C" void kernel_launch(void* const* d_in, const int* in_sizes, int n_in,
                              void* d_out, int out_size) {
    const float* x     = (const float*)d_in[0];
    const void*  ei    = d_in[1];
    const void*  batch = d_in[2];
    const float* W1  = (const float*)d_in[3];
    const float* as1 = (const float*)d_in[4];
    const float* ad1 = (const float*)d_in[5];
    const float* b1  = (const float*)d_in[6];
    const float* W2  = (const float*)d_in[7];
    const float* as2 = (const float*)d_in[8];
    const float* ad2 = (const float*)d_in[9];
    const float* b2  = (const float*)d_in[10];
    const float* W3  = (const float*)d_in[11];
    const float* as3 = (const float*)d_in[12];
    const float* ad3 = (const float*)d_in[13];
    const float* b3  = (const float*)d_in[14];
    const float* Wm1 = (const float*)d_in[15];
    const float* bm1 = (const float*)d_in[16];
    const float* Wm2 = (const float*)d_in[17];
    const float* bm2 = (const float*)d_in[18];
    float* out = (float*)d_out;

    float *bufA, *bufB;
    int *cntp, *offp;
    cudaGetSymbolAddress((void**)&bufA, g_bufA);
    cudaGetSymbolAddress((void**)&bufB, g_bufB);
    cudaGetSymbolAddress((void**)&cntp, g_cnt);
    cudaGetSymbolAddress((void**)&offp, g_off);

    const int TPB = 256;
    int nb_node = (NN + TPB - 1) / TPB;
    int nb_edge = (EE + TPB - 1) / TPB;
    int nb_warp = (NN * 32 + TPB - 1) / TPB;   // one warp per node

    // dtype detection + CSR build (graph identical for all 3 layers)
    k_detect<<<1, 32>>>(ei, batch);
    k_zero<<<nb_node, TPB>>>();
    k_count<<<nb_edge, TPB>>>(ei);
    k_gbounds<<<1, 128>>>(batch);
    k_scan<<<1, 1024>>>(cntp, offp, NN);
    k_fill<<<nb_edge, TPB>>>(ei);

    dim3 gemm_grid(NN / 64, HC / 64);

    // Layer 1
    k_gemm_tc<<<gemm_grid, 128>>>(x, W1, bufA);
    k_alpha<<<nb_warp, TPB>>>(bufA, as1, ad1);
    k_edgew<<<nb_edge, TPB>>>(ei);
    k_gather<true><<<nb_warp, TPB>>>(bufA, b1, bufB);

    // Layer 2
    k_gemm_tc<<<gemm_grid, 128>>>(bufB, W2, bufA);
    k_alpha<<<nb_warp, TPB>>>(bufA, as2, ad2);
    k_edgew<<<nb_edge, TPB>>>(ei);
    k_gather<true><<<nb_warp, TPB>>>(bufA, b2, bufB);

    // Layer 3 (no relu)
    k_gemm_tc<<<gemm_grid, 128>>>(bufB, W3, bufA);
    k_alpha<<<nb_warp, TPB>>>(bufA, as3, ad3);
    k_edgew<<<nb_edge, TPB>>>(ei);
    k_gather<false><<<nb_warp, TPB>>>(bufA, b3, bufB);

    // Pool + MLP
    k_pool<<<GG, HC>>>(bufB);
    k_mlp1<<<GG, NHID>>>(Wm1, bm1);
    k_mlp2<<<GG, NOUT>>>(Wm2, bm2, out);
}

// round 4
// speedup vs baseline: 1.1690x; 1.0713x over previous
#include <cuda_runtime.h>
#include <math.h>
#include <stdint.h>

#define NN   40000
#define EE   640000
#define GG   64
#define HH   4
#define CC   64
#define HC   256
#define NHID 1024
#define NOUT 768
#define NEG_SLOPE 0.2f

// ---------------- static device scratch ----------------
__device__ float g_bufA[(size_t)NN * HC];
__device__ float g_bufB[(size_t)NN * HC];
__device__ float g_as[NN * 4];
__device__ float g_ad[NN * 4];
__device__ int   g_cnt[NN];
__device__ int   g_cur[NN];
__device__ int   g_off[NN + 1];
__device__ int   g_csr[EE];                 // src node, sorted by dst
__device__ int   g_goff[GG + 1];
__device__ float g_pooled[GG * HC];
__device__ float g_hid[GG * NHID];
__device__ int   g_is64_e, g_is64_b;
__device__ int   g_bsum[160];
__device__ int   g_boff[160];
// pre-split weights (hi/lo tf32)
__device__ float g_w1hi[HC * HC], g_w1lo[HC * HC];
__device__ float g_w2hi[HC * HC], g_w2lo[HC * HC];
__device__ float g_w3hi[HC * HC], g_w3lo[HC * HC];

__device__ __forceinline__ float lrelu(float v) {
    return v > 0.f ? v : NEG_SLOPE * v;
}

__device__ __forceinline__ int idx_at(const void* p, long long i, int is64) {
    if (is64) return (int)((const long long*)p)[i];
    return ((const int*)p)[i];
}

__device__ __forceinline__ void split_tf32(float x, float& hi, float& lo) {
    uint32_t u;
    asm("cvt.rna.tf32.f32 %0, %1;" : "=r"(u) : "f"(x));
    hi = __uint_as_float(u);
    float l = x - hi;
    uint32_t ul;
    asm("cvt.rna.tf32.f32 %0, %1;" : "=r"(ul) : "f"(l));
    lo = __uint_as_float(ul);
}

// ---------------- dtype detection ----------------
__global__ void k_detect(const void* ei, const void* batch) {
    if (threadIdx.x != 0 || blockIdx.x != 0) return;
    const int* e32 = (const int*)ei;
    int all0 = 1;
    for (int j = 1; j < 128; j += 2) if (e32[j] != 0) { all0 = 0; break; }
    g_is64_e = all0;
    const int* b32 = (const int*)batch;
    all0 = 1;
    for (int j = NN - 1; j > NN - 65; j -= 2) if (b32[j] != 0) { all0 = 0; break; }
    g_is64_b = all0;
}

// ---------------- prep: zero counters + split all weight matrices ----------------
__global__ void k_prep(const float* __restrict__ W1, const float* __restrict__ W2,
                       const float* __restrict__ W3) {
    int i = blockIdx.x * blockDim.x + threadIdx.x;
    if (i < NN) { g_cnt[i] = 0; g_cur[i] = 0; }
    if (i < (HC * HC) / 4) {
        float4 v1 = ((const float4*)W1)[i];
        float4 v2 = ((const float4*)W2)[i];
        float4 v3 = ((const float4*)W3)[i];
        float4 h1, l1, h2, l2, h3, l3;
        split_tf32(v1.x, h1.x, l1.x); split_tf32(v1.y, h1.y, l1.y);
        split_tf32(v1.z, h1.z, l1.z); split_tf32(v1.w, h1.w, l1.w);
        split_tf32(v2.x, h2.x, l2.x); split_tf32(v2.y, h2.y, l2.y);
        split_tf32(v2.z, h2.z, l2.z); split_tf32(v2.w, h2.w, l2.w);
        split_tf32(v3.x, h3.x, l3.x); split_tf32(v3.y, h3.y, l3.y);
        split_tf32(v3.z, h3.z, l3.z); split_tf32(v3.w, h3.w, l3.w);
        ((float4*)g_w1hi)[i] = h1; ((float4*)g_w1lo)[i] = l1;
        ((float4*)g_w2hi)[i] = h2; ((float4*)g_w2lo)[i] = l2;
        ((float4*)g_w3hi)[i] = h3; ((float4*)g_w3lo)[i] = l3;
    }
}

// ---------------- CSR ----------------
__global__ void k_count(const void* __restrict__ ei) {
    int e = blockIdx.x * blockDim.x + threadIdx.x;
    if (e < EE) atomicAdd(&g_cnt[idx_at(ei, (long long)EE + e, g_is64_e)], 1);
}

__global__ void k_gbounds(const void* __restrict__ batch) {
    int g = threadIdx.x;
    if (g > GG) return;
    int is64 = g_is64_b;
    int lo = 0, hi = NN;
    while (lo < hi) {
        int mid = (lo + hi) >> 1;
        if (idx_at(batch, mid, is64) < g) lo = mid + 1; else hi = mid;
    }
    g_goff[g] = lo;
}

// multi-block scan: phase 1 (per-block exclusive scan + block totals)
__global__ void k_scan1() {
    __shared__ int sd[256];
    int b = blockIdx.x, t = threadIdx.x;
    int i = b * 256 + t;
    int v = (i < NN) ? g_cnt[i] : 0;
    sd[t] = v;
    __syncthreads();
#pragma unroll
    for (int o = 1; o < 256; o <<= 1) {
        int y = (t >= o) ? sd[t - o] : 0;
        __syncthreads();
        sd[t] += y;
        __syncthreads();
    }
    if (i < NN) g_off[i] = sd[t] - v;
    if (t == 255) g_bsum[b] = sd[255];
}

// phase 2: scan the 157 block sums (one block)
__global__ void k_scan2(int nb) {
    __shared__ int sd[256];
    int t = threadIdx.x;
    int v = (t < nb) ? g_bsum[t] : 0;
    sd[t] = v;
    __syncthreads();
#pragma unroll
    for (int o = 1; o < 256; o <<= 1) {
        int y = (t >= o) ? sd[t - o] : 0;
        __syncthreads();
        sd[t] += y;
        __syncthreads();
    }
    if (t < nb) g_boff[t] = sd[t] - v;
    if (t == 0) g_off[NN] = EE;
}

// phase 3: add block offsets
__global__ void k_scan3() {
    int i = blockIdx.x * blockDim.x + threadIdx.x;
    if (i < NN) g_off[i] += g_boff[blockIdx.x];
}

__global__ void k_fill(const void* __restrict__ ei) {
    int e = blockIdx.x * blockDim.x + threadIdx.x;
    if (e >= EE) return;
    int is64 = g_is64_e;
    int s = idx_at(ei, e, is64);
    int d = idx_at(ei, (long long)EE + e, is64);
    int pos = atomicAdd(&g_cur[d], 1);
    g_csr[g_off[d] + pos] = s;
}

// ---------------- tf32 split-precision tensor-core GEMM ----------------
__device__ __forceinline__ void mma_tf32(float* d, const uint32_t* a, const uint32_t* b) {
    asm volatile(
        "mma.sync.aligned.m16n8k8.row.col.f32.tf32.tf32.f32 "
        "{%0,%1,%2,%3}, {%4,%5,%6,%7}, {%8,%9}, {%0,%1,%2,%3};\n"
        : "+f"(d[0]), "+f"(d[1]), "+f"(d[2]), "+f"(d[3])
        : "r"(a[0]), "r"(a[1]), "r"(a[2]), "r"(a[3]), "r"(b[0]), "r"(b[1]));
}

#define AS_STR 36
#define BS_STR 72

__global__ void __launch_bounds__(128) k_gemm_tc(const float* __restrict__ A,
                                                 const float* __restrict__ Bhi,
                                                 const float* __restrict__ Blo,
                                                 float* __restrict__ C) {
    __shared__ float As_hi[64][AS_STR], As_lo[64][AS_STR];
    __shared__ float Bs_hi[32][BS_STR], Bs_lo[32][BS_STR];

    int tid = threadIdx.x;
    int warp = tid >> 5, lane = tid & 31;
    int wm = (warp & 1) * 32;
    int wn = (warp >> 1) * 32;
    int lm = lane >> 2;
    int lk = lane & 3;
    int row0 = blockIdx.x * 64;
    int col0 = blockIdx.y * 64;

    float acc[2][4][4];
#pragma unroll
    for (int mt = 0; mt < 2; mt++)
#pragma unroll
        for (int nt = 0; nt < 4; nt++)
#pragma unroll
            for (int r = 0; r < 4; r++) acc[mt][nt][r] = 0.f;

    int am = tid >> 1;
    int akseg = (tid & 1) * 16;
    int bk = tid >> 2;
    int bnseg = (tid & 3) * 16;

    for (int k0 = 0; k0 < 256; k0 += 32) {
#pragma unroll
        for (int i = 0; i < 4; i++) {
            int k = akseg + i * 4;
            float4 v = *(const float4*)(A + (size_t)(row0 + am) * 256 + k0 + k);
            float4 vh, vl;
            split_tf32(v.x, vh.x, vl.x);
            split_tf32(v.y, vh.y, vl.y);
            split_tf32(v.z, vh.z, vl.z);
            split_tf32(v.w, vh.w, vl.w);
            *(float4*)&As_hi[am][k] = vh;
            *(float4*)&As_lo[am][k] = vl;
        }
#pragma unroll
        for (int i = 0; i < 4; i++) {
            int n = bnseg + i * 4;
            size_t gi = (size_t)(k0 + bk) * 256 + col0 + n;
            *(float4*)&Bs_hi[bk][n] = *(const float4*)(Bhi + gi);
            *(float4*)&Bs_lo[bk][n] = *(const float4*)(Blo + gi);
        }
        __syncthreads();

#pragma unroll
        for (int kk = 0; kk < 32; kk += 8) {
            uint32_t ah[2][4], al[2][4];
#pragma unroll
            for (int mt = 0; mt < 2; mt++) {
                int r = wm + mt * 16 + lm;
                ah[mt][0] = __float_as_uint(As_hi[r][kk + lk]);
                ah[mt][1] = __float_as_uint(As_hi[r + 8][kk + lk]);
                ah[mt][2] = __float_as_uint(As_hi[r][kk + lk + 4]);
                ah[mt][3] = __float_as_uint(As_hi[r + 8][kk + lk + 4]);
                al[mt][0] = __float_as_uint(As_lo[r][kk + lk]);
                al[mt][1] = __float_as_uint(As_lo[r + 8][kk + lk]);
                al[mt][2] = __float_as_uint(As_lo[r][kk + lk + 4]);
                al[mt][3] = __float_as_uint(As_lo[r + 8][kk + lk + 4]);
            }
            uint32_t bh[4][2], bl[4][2];
#pragma unroll
            for (int nt = 0; nt < 4; nt++) {
                int c = wn + nt * 8 + lm;
                bh[nt][0] = __float_as_uint(Bs_hi[kk + lk][c]);
                bh[nt][1] = __float_as_uint(Bs_hi[kk + lk + 4][c]);
                bl[nt][0] = __float_as_uint(Bs_lo[kk + lk][c]);
                bl[nt][1] = __float_as_uint(Bs_lo[kk + lk + 4][c]);
            }
#pragma unroll
            for (int mt = 0; mt < 2; mt++)
#pragma unroll
                for (int nt = 0; nt < 4; nt++) {
                    mma_tf32(acc[mt][nt], ah[mt], bh[nt]);
                    mma_tf32(acc[mt][nt], ah[mt], bl[nt]);
                    mma_tf32(acc[mt][nt], al[mt], bh[nt]);
                }
        }
        __syncthreads();
    }

#pragma unroll
    for (int mt = 0; mt < 2; mt++) {
        int r = row0 + wm + mt * 16 + lm;
#pragma unroll
        for (int nt = 0; nt < 4; nt++) {
            int c = col0 + wn + nt * 8 + lk * 2;
            *(float2*)(C + (size_t)r * 256 + c)       = make_float2(acc[mt][nt][0], acc[mt][nt][1]);
            *(float2*)(C + (size_t)(r + 8) * 256 + c) = make_float2(acc[mt][nt][2], acc[mt][nt][3]);
        }
    }
}

// ---------------- per-node attention scalars ----------------
__global__ void k_alpha(const float* __restrict__ h, const float* __restrict__ a_s,
                        const float* __restrict__ a_d) {
    int gw = (blockIdx.x * blockDim.x + threadIdx.x) >> 5;
    int lane = threadIdx.x & 31;
    if (gw >= NN) return;
    const float* row = h + (size_t)gw * HC;
#pragma unroll
    for (int hh = 0; hh < HH; hh++) {
        float v1 = row[hh * 64 + lane];
        float v2 = row[hh * 64 + 32 + lane];
        float ps = v1 * __ldg(&a_s[hh * 64 + lane]) + v2 * __ldg(&a_s[hh * 64 + 32 + lane]);
        float pd = v1 * __ldg(&a_d[hh * 64 + lane]) + v2 * __ldg(&a_d[hh * 64 + 32 + lane]);
#pragma unroll
        for (int o = 16; o > 0; o >>= 1) {
            ps += __shfl_down_sync(0xffffffffu, ps, o);
            pd += __shfl_down_sync(0xffffffffu, pd, o);
        }
        if (lane == 0) {
            g_as[gw * 4 + hh] = ps;
            g_ad[gw * 4 + hh] = pd;
        }
    }
}

// ---------------- warp-per-node gather with inline softmax weights ----------------
template <bool RELU>
__global__ void k_gather(const float* __restrict__ h, const float* __restrict__ bias,
                         float* __restrict__ out) {
    int gw = (blockIdx.x * blockDim.x + threadIdx.x) >> 5;
    int lane = threadIdx.x & 31;
    if (gw >= NN) return;
    int s0 = g_off[gw], s1 = g_off[gw + 1];
    float4 dv = *(const float4*)(g_ad + gw * 4);   // alpha_dst of this node
    float acc[8];
#pragma unroll
    for (int k = 0; k < 8; k++) acc[k] = 0.f;
    float den0 = 0.f, den1 = 0.f, den2 = 0.f, den3 = 0.f;

    for (int i = s0; i < s1; i++) {
        int s = __ldg(&g_csr[i]);
        float4 a = __ldg((const float4*)g_as + s);
        float w0 = __expf(lrelu(a.x + dv.x));
        float w1 = __expf(lrelu(a.y + dv.y));
        float w2 = __expf(lrelu(a.z + dv.z));
        float w3 = __expf(lrelu(a.w + dv.w));
        den0 += w0; den1 += w1; den2 += w2; den3 += w3;
        const float* hs = h + (size_t)s * HC;
        float wl[4] = {w0, w1, w2, w3};
#pragma unroll
        for (int k = 0; k < 8; k++) {
            acc[k] += wl[k >> 1] * __ldg(&hs[lane + 32 * k]);
        }
    }
    // self loop
    float4 av = *(const float4*)(g_as + gw * 4);
    float ws[4];
    ws[0] = __expf(lrelu(av.x + dv.x));
    ws[1] = __expf(lrelu(av.y + dv.y));
    ws[2] = __expf(lrelu(av.z + dv.z));
    ws[3] = __expf(lrelu(av.w + dv.w));
    float den[4] = {den0 + ws[0], den1 + ws[1], den2 + ws[2], den3 + ws[3]};
    const float* hn = h + (size_t)gw * HC;
    float* orow = out + (size_t)gw * HC;
#pragma unroll
    for (int k = 0; k < 8; k++) {
        int c = lane + 32 * k;
        int hh = k >> 1;
        float v = (acc[k] + ws[hh] * __ldg(&hn[c])) / den[hh] + __ldg(&bias[c]);
        if (RELU) v = fmaxf(v, 0.f);
        orow[c] = v;
    }
}

// ---------------- pooling + MLP head ----------------
__global__ void k_pool(const float* __restrict__ h3) {
    int g = blockIdx.x;
    int c = threadIdx.x;
    int s = g_goff[g], e = g_goff[g + 1];
    float sum = 0.f;
    for (int n = s; n < e; n++) sum += h3[(size_t)n * HC + c];
    float cntf = (float)(e - s);
    g_pooled[g * HC + c] = sum / fmaxf(cntf, 1.0f);
}

__global__ void k_mlp1(const float* __restrict__ Wm1, const float* __restrict__ bm1) {
    __shared__ float sp[HC];
    int g = blockIdx.x;
    int j = threadIdx.x;
    if (j < HC) sp[j] = g_pooled[g * HC + j];
    __syncthreads();
    float acc = __ldg(&bm1[j]);
    for (int k = 0; k < HC; k++) acc += sp[k] * __ldg(&Wm1[(size_t)k * NHID + j]);
    g_hid[g * NHID + j] = fmaxf(acc, 0.f);
}

__global__ void k_mlp2(const float* __restrict__ Wm2, const float* __restrict__ bm2,
                       float* __restrict__ out) {
    __shared__ float sp[NHID];
    int g = blockIdx.x;
    int j = threadIdx.x;
    for (int k = j; k < NHID; k += NOUT) sp[k] = g_hid[g * NHID + k];
    __syncthreads();
    float acc = __ldg(&bm2[j]);
    for (int k = 0; k < NHID; k++) acc += sp[k] * __ldg(&Wm2[(size_t)k * NOUT + j]);
    out[g * NOUT + j] = acc;
}

// ---------------- launch ----------------
extern "C" void kernel_launch(void* const* d_in, const int* in_sizes, int n_in,
                              void* d_out, int out_size) {
    const float* x     = (const float*)d_in[0];
    const void*  ei    = d_in[1];
    const void*  batch = d_in[2];
    const float* W1  = (const float*)d_in[3];
    const float* as1 = (const float*)d_in[4];
    const float* ad1 = (const float*)d_in[5];
    const float* b1  = (const float*)d_in[6];
    const float* W2  = (const float*)d_in[7];
    const float* as2 = (const float*)d_in[8];
    const float* ad2 = (const float*)d_in[9];
    const float* b2  = (const float*)d_in[10];
    const float* W3  = (const float*)d_in[11];
    const float* as3 = (const float*)d_in[12];
    const float* ad3 = (const float*)d_in[13];
    const float* b3  = (const float*)d_in[14];
    const float* Wm1 = (const float*)d_in[15];
    const float* bm1 = (const float*)d_in[16];
    const float* Wm2 = (const float*)d_in[17];
    const float* bm2 = (const float*)d_in[18];
    float* out = (float*)d_out;

    float *bufA, *bufB, *w1hi, *w1lo, *w2hi, *w2lo, *w3hi, *w3lo;
    cudaGetSymbolAddress((void**)&bufA, g_bufA);
    cudaGetSymbolAddress((void**)&bufB, g_bufB);
    cudaGetSymbolAddress((void**)&w1hi, g_w1hi);
    cudaGetSymbolAddress((void**)&w1lo, g_w1lo);
    cudaGetSymbolAddress((void**)&w2hi, g_w2hi);
    cudaGetSymbolAddress((void**)&w2lo, g_w2lo);
    cudaGetSymbolAddress((void**)&w3hi, g_w3hi);
    cudaGetSymbolAddress((void**)&w3lo, g_w3lo);

    const int TPB = 256;
    int nb_node = (NN + TPB - 1) / TPB;     // 157
    int nb_edge = (EE + TPB - 1) / TPB;
    int nb_warp = (NN * 32 + TPB - 1) / TPB;

    dim3 gemm_grid(NN / 64, HC / 64);

    // launch index 3 (0-based) is what ncu captures -> place gemm there
    k_detect<<<1, 32>>>(ei, batch);                       // 0
    k_prep<<<nb_node, TPB>>>(W1, W2, W3);                 // 1
    k_count<<<nb_edge, TPB>>>(ei);                        // 2
    k_gemm_tc<<<gemm_grid, 128>>>(x, w1hi, w1lo, bufA);   // 3  <- profiled
    k_gbounds<<<1, 128>>>(batch);                         // 4
    k_scan1<<<nb_node, TPB>>>();                          // 5
    k_scan2<<<1, 256>>>(nb_node);                         // 6
    k_scan3<<<nb_node, TPB>>>();                          // 7
    k_fill<<<nb_edge, TPB>>>(ei);                         // 8

    // Layer 1 (gemm already done)
    k_alpha<<<nb_warp, TPB>>>(bufA, as1, ad1);
    k_gather<true><<<nb_warp, TPB>>>(bufA, b1, bufB);

    // Layer 2
    k_gemm_tc<<<gemm_grid, 128>>>(bufB, w2hi, w2lo, bufA);
    k_alpha<<<nb_warp, TPB>>>(bufA, as2, ad2);
    k_gather<true><<<nb_warp, TPB>>>(bufA, b2, bufB);

    // Layer 3 (no relu)
    k_gemm_tc<<<gemm_grid, 128>>>(bufB, w3hi, w3lo, bufA);
    k_alpha<<<nb_warp, TPB>>>(bufA, as3, ad3);
    k_gather<false><<<nb_warp, TPB>>>(bufA, b3, bufB);

    // Pool + MLP
    k_pool<<<GG, HC>>>(bufB);
    k_mlp1<<<GG, NHID>>>(Wm1, bm1);
    k_mlp2<<<GG, NOUT>>>(Wm2, bm2, out);
}